// round 2
// baseline (speedup 1.0000x reference)
#include <cuda_runtime.h>
#include <math.h>

#define NROWS 262144
#define C 256
#define S 16

// Scratch (allocation-free rule: __device__ globals)
__device__ float g_segsum[S * C];   // per-segment column sums
__device__ float g_ctab[S * C];     // folded per-segment constant: (h@W1b + b1)*sc + beta - mean*sc
__device__ float g_scale[C];        // BN scale: gamma * rsqrt(var+eps)

// ---------------------------------------------------------------------------
// k0: zero the segment accumulator
// ---------------------------------------------------------------------------
__global__ void k0_zero() {
    int i = blockIdx.x * blockDim.x + threadIdx.x;
    if (i < S * C) g_segsum[i] = 0.0f;
}

// ---------------------------------------------------------------------------
// k1: segment sums. CTA = 128 rows, thread = one column. Rows within a CTA
// share the segment id, so no divergence; flush partial sums with atomicAdd
// only at segment boundaries (<= ~2 per CTA).
// ---------------------------------------------------------------------------
__global__ void __launch_bounds__(256) k1_segsum(const float* __restrict__ x,
                                                 const int* __restrict__ o32) {
    __shared__ int so[S];
    if (threadIdx.x < S) {
        int stride = (o32[1] == 0) ? 2 : 1;  // int64 vs int32 layout detection
        so[threadIdx.x] = o32[threadIdx.x * stride];
    }
    __syncthreads();

    int t = threadIdx.x;
    int g0 = blockIdx.x * 128;
    int s = 0;
    while (g0 >= so[s]) s++;

    int r = 0;
    while (r < 128) {
        int end = so[s] - g0;
        if (end > 128) end = 128;
        float acc = 0.0f;
        for (; r + 4 <= end; r += 4) {
            float a0 = __ldg(&x[(size_t)(g0 + r + 0) * C + t]);
            float a1 = __ldg(&x[(size_t)(g0 + r + 1) * C + t]);
            float a2 = __ldg(&x[(size_t)(g0 + r + 2) * C + t]);
            float a3 = __ldg(&x[(size_t)(g0 + r + 3) * C + t]);
            acc += a0 + a1 + a2 + a3;
        }
        for (; r < end; r++) acc += __ldg(&x[(size_t)(g0 + r) * C + t]);
        atomicAdd(&g_segsum[s * C + t], acc);
        s++;
    }
}

// ---------------------------------------------------------------------------
// k2: per-segment tiny math. CTA s: mean -> h = relu(mean@W2 + b2) ->
// c[s] = (h@W1b + b1)*sc + beta - run_mean*sc.  Also writes g_scale.
// ---------------------------------------------------------------------------
__global__ void __launch_bounds__(256) k2_tiny(const int* __restrict__ o32,
                                               const float* __restrict__ W2,
                                               const float* __restrict__ b2,
                                               const float* __restrict__ W1,
                                               const float* __restrict__ b1,
                                               const float* __restrict__ gamma,
                                               const float* __restrict__ beta,
                                               const float* __restrict__ rm,
                                               const float* __restrict__ rv) {
    __shared__ float mean_s[C];
    __shared__ float h_s[C];
    int s = blockIdx.x;
    int t = threadIdx.x;

    int stride = (o32[1] == 0) ? 2 : 1;
    int oe = o32[s * stride];
    int ob = (s > 0) ? o32[(s - 1) * stride] : 0;
    float cnt = (float)(oe - ob);

    mean_s[t] = g_segsum[s * C + t] / cnt;
    __syncthreads();

    float acc = 0.0f;
#pragma unroll 8
    for (int k = 0; k < C; k++) acc = fmaf(mean_s[k], __ldg(&W2[k * C + t]), acc);
    float hv = fmaxf(acc + __ldg(&b2[t]), 0.0f);
    h_s[t] = hv;
    __syncthreads();

    float g = 0.0f;
#pragma unroll 8
    for (int k = 0; k < C; k++) g = fmaf(h_s[k], __ldg(&W1[(size_t)(C + k) * C + t]), g);

    float sc = gamma[t] * rsqrtf(rv[t] + 1e-5f);
    g_ctab[s * C + t] = (g + b1[t]) * sc + beta[t] - rm[t] * sc;
    if (s == 0) g_scale[t] = sc;
}

// ---------------------------------------------------------------------------
// k3: main GEMM + fused epilogue.
// out[i,:] = relu( (x[i,:] @ W1a) * sc + c[seg(i),:] )
// Tile: BM=64 rows x BN=256 cols (full width -> x read exactly once),
// BK=16, 256 threads, 8x8 register tile per thread, double-buffered smem.
// ---------------------------------------------------------------------------
#define BM 64
#define BK 16
#define APAD 68  // 16B-aligned row pad for transposed A tile

__global__ void __launch_bounds__(256, 2) k3_gemm(const float* __restrict__ x,
                                                  const float* __restrict__ W1,
                                                  const int* __restrict__ o32,
                                                  float* __restrict__ out) {
    __shared__ float As[2][BK][APAD];   // transposed: As[k][row]
    __shared__ float Bs[2][BK][C];      // Bs[k][col]
    __shared__ int so[S];

    int tid = threadIdx.x;
    if (tid < S) {
        int stride = (o32[1] == 0) ? 2 : 1;
        so[tid] = o32[tid * stride];
    }

    int m0 = blockIdx.x * BM;
    int tr = tid >> 5;    // 0..7  (row group)
    int tc = tid & 31;    // 0..31 (col group)
    int arow = tid >> 2;  // 0..63 : A-load row
    int aq = tid & 3;     // 0..3  : A-load k-quad
    int kb = tid >> 4;    // 0..15 : B-load k
    int cb = tid & 15;    // 0..15 : B-load col group

    const float* aptr = x + (size_t)(m0 + arow) * C + aq * 4;
    const float* bptr = W1 + (size_t)kb * C + cb * 4;

    float acc[8][8];
#pragma unroll
    for (int i = 0; i < 8; i++)
#pragma unroll
        for (int j = 0; j < 8; j++) acc[i][j] = 0.0f;

    // prefetch tile 0
    {
        float4 av = *(const float4*)aptr;
        As[0][aq * 4 + 0][arow] = av.x;
        As[0][aq * 4 + 1][arow] = av.y;
        As[0][aq * 4 + 2][arow] = av.z;
        As[0][aq * 4 + 3][arow] = av.w;
#pragma unroll
        for (int j = 0; j < 4; j++) {
            float4 bv = *(const float4*)(bptr + j * 64);
            *(float4*)&Bs[0][kb][cb * 4 + j * 64] = bv;
        }
    }
    __syncthreads();

#pragma unroll 1
    for (int t = 0; t < 16; t++) {
        int buf = t & 1;
        float4 av;
        float4 bv[4];
        if (t < 15) {
            av = *(const float4*)(aptr + (t + 1) * BK);
#pragma unroll
            for (int j = 0; j < 4; j++)
                bv[j] = *(const float4*)(bptr + (size_t)(t + 1) * BK * C + j * 64);
        }
#pragma unroll
        for (int kk = 0; kk < BK; kk++) {
            float ar[8], bc[8];
            *(float4*)&ar[0] = *(const float4*)&As[buf][kk][tr * 4];
            *(float4*)&ar[4] = *(const float4*)&As[buf][kk][32 + tr * 4];
            *(float4*)&bc[0] = *(const float4*)&Bs[buf][kk][tc * 4];
            *(float4*)&bc[4] = *(const float4*)&Bs[buf][kk][128 + tc * 4];
#pragma unroll
            for (int i = 0; i < 8; i++)
#pragma unroll
                for (int j = 0; j < 8; j++)
                    acc[i][j] = fmaf(ar[i], bc[j], acc[i][j]);
        }
        if (t < 15) {
            int nb = buf ^ 1;
            As[nb][aq * 4 + 0][arow] = av.x;
            As[nb][aq * 4 + 1][arow] = av.y;
            As[nb][aq * 4 + 2][arow] = av.z;
            As[nb][aq * 4 + 3][arow] = av.w;
#pragma unroll
            for (int j = 0; j < 4; j++)
                *(float4*)&Bs[nb][kb][cb * 4 + j * 64] = bv[j];
            __syncthreads();
        }
    }

    // fused epilogue: BN scale + per-segment constant + ReLU
    float scv[8];
#pragma unroll
    for (int j = 0; j < 8; j++) {
        int col = (j < 4) ? (tc * 4 + j) : (128 + tc * 4 + (j - 4));
        scv[j] = g_scale[col];
    }
#pragma unroll
    for (int i = 0; i < 8; i++) {
        int gr = m0 + ((i < 4) ? (tr * 4 + i) : (32 + tr * 4 + (i - 4)));
        int s = 0;
        while (gr >= so[s]) s++;
        const float* crow = g_ctab + s * C;
        float4 o0, o1;
        int c0 = tc * 4;
        int c1 = 128 + tc * 4;
        o0.x = fmaxf(fmaf(acc[i][0], scv[0], crow[c0 + 0]), 0.0f);
        o0.y = fmaxf(fmaf(acc[i][1], scv[1], crow[c0 + 1]), 0.0f);
        o0.z = fmaxf(fmaf(acc[i][2], scv[2], crow[c0 + 2]), 0.0f);
        o0.w = fmaxf(fmaf(acc[i][3], scv[3], crow[c0 + 3]), 0.0f);
        o1.x = fmaxf(fmaf(acc[i][4], scv[4], crow[c1 + 0]), 0.0f);
        o1.y = fmaxf(fmaf(acc[i][5], scv[5], crow[c1 + 1]), 0.0f);
        o1.z = fmaxf(fmaf(acc[i][6], scv[6], crow[c1 + 2]), 0.0f);
        o1.w = fmaxf(fmaf(acc[i][7], scv[7], crow[c1 + 3]), 0.0f);
        *(float4*)&out[(size_t)gr * C + c0] = o0;
        *(float4*)&out[(size_t)gr * C + c1] = o1;
    }
}

// ---------------------------------------------------------------------------
extern "C" void kernel_launch(void* const* d_in, const int* in_sizes, int n_in,
                              void* d_out, int out_size) {
    const float* x     = (const float*)d_in[0];
    const int*   o     = (const int*)d_in[1];   // int32 or int64 (auto-detected on device)
    const float* W2    = (const float*)d_in[2];
    const float* b2    = (const float*)d_in[3];
    const float* W1    = (const float*)d_in[4];
    const float* b1    = (const float*)d_in[5];
    const float* gamma = (const float*)d_in[6];
    const float* beta  = (const float*)d_in[7];
    const float* rm    = (const float*)d_in[8];
    const float* rv    = (const float*)d_in[9];
    float* out = (float*)d_out;

    k0_zero<<<16, 256>>>();
    k1_segsum<<<NROWS / 128, 256>>>(x, o);
    k2_tiny<<<S, 256>>>(o, W2, b2, W1, b1, gamma, beta, rm, rv);
    k3_gemm<<<NROWS / BM, 256>>>(x, W1, o, out);
}

// round 4
// speedup vs baseline: 1.8342x; 1.8342x over previous
#include <cuda_runtime.h>
#include <cuda_bf16.h>
#include <cstdint>
#include <math.h>

#define NROWS 262144
#define C 256
#define S 16

#define BM 128
#define BN 256
#define BK 32
#define NCHUNK 8          // K=256 / BK
#define NT 512            // threads per CTA
#define AP 40             // A smem row stride in halves (128+pad? no: 32 k + 8 pad)
#define BP 264            // B smem row stride in halves (256 + 8 pad)

// ---------------- scratch ---------------------------------------------------
__device__ float g_segsum[S * C];
__device__ float g_ctab[S * C];
__device__ float g_scale[C];
// B image: [chunk][hi/lo][k=32][BP] bf16, exactly the smem layout per chunk
__device__ __nv_bfloat16 g_Bimg[NCHUNK * 2 * 32 * BP];

// ---------------- helpers ---------------------------------------------------
__device__ __forceinline__ uint32_t smem_u32(const void* p) {
    uint32_t a;
    asm("{ .reg .u64 t; cvta.to.shared.u64 t, %1; cvt.u32.u64 %0, t; }" : "=r"(a) : "l"(p));
    return a;
}
#define CP_ASYNC16(dst, src) asm volatile("cp.async.cg.shared.global [%0], [%1], 16;" :: "r"(dst), "l"(src))
#define CP_COMMIT() asm volatile("cp.async.commit_group;" ::: "memory")
#define CP_WAIT0()  asm volatile("cp.async.wait_group 0;" ::: "memory")

#define LDSM_X4(r0, r1, r2, r3, addr) \
    asm volatile("ldmatrix.sync.aligned.m8n8.x4.shared.b16 {%0,%1,%2,%3}, [%4];" \
                 : "=r"(r0), "=r"(r1), "=r"(r2), "=r"(r3) : "r"(addr))
#define LDSM_X2_T(r0, r1, addr) \
    asm volatile("ldmatrix.sync.aligned.m8n8.x2.trans.shared.b16 {%0,%1}, [%2];" \
                 : "=r"(r0), "=r"(r1) : "r"(addr))

#define MMA_BF16(d, a, b) \
    asm volatile("mma.sync.aligned.m16n8k16.row.col.f32.bf16.bf16.f32 " \
                 "{%0,%1,%2,%3}, {%4,%5,%6,%7}, {%8,%9}, {%0,%1,%2,%3};" \
                 : "+f"((d)[0]), "+f"((d)[1]), "+f"((d)[2]), "+f"((d)[3]) \
                 : "r"((a)[0]), "r"((a)[1]), "r"((a)[2]), "r"((a)[3]), "r"((b)[0]), "r"((b)[1]))

__device__ __forceinline__ uint32_t pack2(__nv_bfloat16 a, __nv_bfloat16 b) {
    __nv_bfloat162 v;
    v.x = a; v.y = b;
    return *reinterpret_cast<uint32_t*>(&v);
}

// ---------------------------------------------------------------------------
__global__ void k0_zero() {
    int i = blockIdx.x * blockDim.x + threadIdx.x;
    if (i < S * C) g_segsum[i] = 0.0f;
}

// W1a (rows 0..255) -> bf16 hi/lo chunk images with padded rows
__global__ void kw_split(const float* __restrict__ W1) {
    int k = blockIdx.x;   // 0..255
    int n = threadIdx.x;  // 0..255
    float w = W1[k * C + n];
    __nv_bfloat16 h = __float2bfloat16(w);
    __nv_bfloat16 l = __float2bfloat16(w - __bfloat162float(h));
    int c = k >> 5, kk = k & 31;
    g_Bimg[((c * 2 + 0) * 32 + kk) * BP + n] = h;
    g_Bimg[((c * 2 + 1) * 32 + kk) * BP + n] = l;
    if (n < BP - 256) {  // zero pad columns
        g_Bimg[((c * 2 + 0) * 32 + kk) * BP + 256 + n] = __float2bfloat16(0.0f);
        g_Bimg[((c * 2 + 1) * 32 + kk) * BP + 256 + n] = __float2bfloat16(0.0f);
    }
}

// segment sums (unchanged, passed R2)
__global__ void __launch_bounds__(256) k1_segsum(const float* __restrict__ x,
                                                 const int* __restrict__ o32) {
    __shared__ int so[S];
    if (threadIdx.x < S) {
        int stride = (o32[1] == 0) ? 2 : 1;
        so[threadIdx.x] = o32[threadIdx.x * stride];
    }
    __syncthreads();
    int t = threadIdx.x;
    int g0 = blockIdx.x * 128;
    int s = 0;
    while (g0 >= so[s]) s++;
    int r = 0;
    while (r < 128) {
        int end = so[s] - g0;
        if (end > 128) end = 128;
        float acc = 0.0f;
        for (; r + 4 <= end; r += 4) {
            acc += __ldg(&x[(size_t)(g0 + r + 0) * C + t]) + __ldg(&x[(size_t)(g0 + r + 1) * C + t]) +
                   __ldg(&x[(size_t)(g0 + r + 2) * C + t]) + __ldg(&x[(size_t)(g0 + r + 3) * C + t]);
        }
        for (; r < end; r++) acc += __ldg(&x[(size_t)(g0 + r) * C + t]);
        atomicAdd(&g_segsum[s * C + t], acc);
        s++;
    }
}

// per-segment tiny math (unchanged, passed R2)
__global__ void __launch_bounds__(256) k2_tiny(const int* __restrict__ o32,
                                               const float* __restrict__ W2,
                                               const float* __restrict__ b2,
                                               const float* __restrict__ W1,
                                               const float* __restrict__ b1,
                                               const float* __restrict__ gamma,
                                               const float* __restrict__ beta,
                                               const float* __restrict__ rm,
                                               const float* __restrict__ rv) {
    __shared__ float mean_s[C];
    __shared__ float h_s[C];
    int s = blockIdx.x, t = threadIdx.x;
    int stride = (o32[1] == 0) ? 2 : 1;
    int oe = o32[s * stride];
    int ob = (s > 0) ? o32[(s - 1) * stride] : 0;
    float cnt = (float)(oe - ob);
    mean_s[t] = g_segsum[s * C + t] / cnt;
    __syncthreads();
    float acc = 0.0f;
#pragma unroll 8
    for (int k = 0; k < C; k++) acc = fmaf(mean_s[k], __ldg(&W2[k * C + t]), acc);
    h_s[t] = fmaxf(acc + __ldg(&b2[t]), 0.0f);
    __syncthreads();
    float g = 0.0f;
#pragma unroll 8
    for (int k = 0; k < C; k++) g = fmaf(h_s[k], __ldg(&W1[(size_t)(C + k) * C + t]), g);
    float sc = gamma[t] * rsqrtf(rv[t] + 1e-5f);
    g_ctab[s * C + t] = (g + b1[t]) * sc + beta[t] - rm[t] * sc;
    if (s == 0) g_scale[t] = sc;
}

// ---------------------------------------------------------------------------
// k3: mma.sync bf16 3-term split GEMM + fused epilogue.
// smem: [so 128B][A: 2 buf x 2 planes x 128 x AP halves][B: 2 x 2 x 32 x BP]
// ---------------------------------------------------------------------------
#define A_PLANE (BM * AP)            // halves
#define B_PLANE (32 * BP)            // halves
#define A_OFF 128                    // bytes
#define B_OFF (A_OFF + 2 * 2 * A_PLANE * 2)
#define K3_SMEM (B_OFF + 2 * 2 * B_PLANE * 2 + 128)

__global__ void __launch_bounds__(NT, 1) k3_mma(const float* __restrict__ x,
                                                const int* __restrict__ o32,
                                                float* __restrict__ out) {
    extern __shared__ char smem[];
    uint32_t sbase = smem_u32(smem);
    int* so_s = (int*)smem;
    __nv_bfloat16* Asm = (__nv_bfloat16*)(smem + A_OFF);
    __nv_bfloat16* Bsm = (__nv_bfloat16*)(smem + B_OFF);
    const uint32_t aA = sbase + A_OFF;
    const uint32_t aB = sbase + B_OFF;

    int tid = threadIdx.x;
    int lane = tid & 31;
    int wid = tid >> 5;
    int wm = wid >> 3;   // 0..1
    int wn = wid & 7;    // 0..7
    int m0 = blockIdx.x * BM;

    if (tid < S) {
        int stride = (o32[1] == 0) ? 2 : 1;
        so_s[tid] = o32[tid * stride];
    }

    // A load geometry: row = tid>>2 (0..127), colb = (tid&3)*8
    int arow = tid >> 2;
    int acolb = (tid & 3) * 8;
    const float* agp = x + (size_t)(m0 + arow) * C + acolb;

    float acc[4][4][4];
#pragma unroll
    for (int i = 0; i < 4; i++)
#pragma unroll
        for (int j = 0; j < 4; j++)
#pragma unroll
            for (int r = 0; r < 4; r++) acc[i][j][r] = 0.0f;

    // lane-dependent ldmatrix byte offsets (within a buffer)
    uint32_t aoff[4];
#pragma unroll
    for (int ms = 0; ms < 4; ms++)
        aoff[ms] = (uint32_t)(((wm * 64 + ms * 16 + (lane & 15)) * AP + ((lane >> 4) << 3)) * 2);
    uint32_t boff[4];
#pragma unroll
    for (int ns = 0; ns < 4; ns++)
        boff[ns] = (uint32_t)(((lane & 15) * BP + wn * 32 + ns * 8) * 2);

    float4 pre0, pre1;

    // ---- prologue: chunk 0 ----
    pre0 = __ldg((const float4*)(agp + 0));
    pre1 = __ldg((const float4*)(agp + 4));
    {
        const char* src = (const char*)g_Bimg;  // chunk 0
        uint32_t dst = aB;                      // buf 0
        for (int i = tid; i < (2 * B_PLANE * 2) / 16; i += NT)
            CP_ASYNC16(dst + i * 16, src + i * 16);
        CP_COMMIT();
    }
    // convert + STS A chunk 0 into buf 0
    {
        __nv_bfloat16* dh = Asm + (size_t)arow * AP + acolb;            // hi plane buf0
        __nv_bfloat16* dl = dh + A_PLANE;                                // lo plane buf0
#pragma unroll
        for (int half4 = 0; half4 < 2; half4++) {
            float4 v = half4 ? pre1 : pre0;
            __nv_bfloat16 h0 = __float2bfloat16(v.x), h1 = __float2bfloat16(v.y);
            __nv_bfloat16 h2 = __float2bfloat16(v.z), h3 = __float2bfloat16(v.w);
            __nv_bfloat16 l0 = __float2bfloat16(v.x - __bfloat162float(h0));
            __nv_bfloat16 l1 = __float2bfloat16(v.y - __bfloat162float(h1));
            __nv_bfloat16 l2 = __float2bfloat16(v.z - __bfloat162float(h2));
            __nv_bfloat16 l3 = __float2bfloat16(v.w - __bfloat162float(h3));
            *(uint2*)(dh + half4 * 4) = make_uint2(pack2(h0, h1), pack2(h2, h3));
            *(uint2*)(dl + half4 * 4) = make_uint2(pack2(l0, l1), pack2(l2, l3));
        }
    }
    CP_WAIT0();
    __syncthreads();

#pragma unroll 1
    for (int c = 0; c < NCHUNK; c++) {
        int buf = c & 1;
        uint32_t abuf = aA + (uint32_t)(buf * 2 * A_PLANE * 2);
        uint32_t bbuf = aB + (uint32_t)(buf * 2 * B_PLANE * 2);

        // prefetch chunk c+1
        if (c < NCHUNK - 1) {
            pre0 = __ldg((const float4*)(agp + (c + 1) * BK + 0));
            pre1 = __ldg((const float4*)(agp + (c + 1) * BK + 4));
            const char* src = (const char*)(g_Bimg + (size_t)(c + 1) * 2 * B_PLANE);
            uint32_t dst = aB + (uint32_t)((buf ^ 1) * 2 * B_PLANE * 2);
            for (int i = tid; i < (2 * B_PLANE * 2) / 16; i += NT)
                CP_ASYNC16(dst + i * 16, src + i * 16);
            CP_COMMIT();
        }

        // ---- compute chunk c ----
#pragma unroll
        for (int kk = 0; kk < BK; kk += 16) {
            uint32_t bh[4][2], bl[4][2];
#pragma unroll
            for (int ns = 0; ns < 4; ns++) {
                uint32_t ad = bbuf + boff[ns] + (uint32_t)(kk * BP * 2);
                LDSM_X2_T(bh[ns][0], bh[ns][1], ad);
                LDSM_X2_T(bl[ns][0], bl[ns][1], ad + (uint32_t)(B_PLANE * 2));
            }
#pragma unroll
            for (int ms = 0; ms < 4; ms++) {
                uint32_t ah[4], al[4];
                uint32_t ad = abuf + aoff[ms] + (uint32_t)(kk * 2);
                LDSM_X4(ah[0], ah[1], ah[2], ah[3], ad);
                LDSM_X4(al[0], al[1], al[2], al[3], ad + (uint32_t)(A_PLANE * 2));
#pragma unroll
                for (int ns = 0; ns < 4; ns++) {
                    MMA_BF16(acc[ms][ns], ah, bh[ns]);
                    MMA_BF16(acc[ms][ns], ah, bl[ns]);
                    MMA_BF16(acc[ms][ns], al, bh[ns]);
                }
            }
        }

        // store prefetched A into next buffer, wait B
        if (c < NCHUNK - 1) {
            __nv_bfloat16* dh = Asm + (size_t)(buf ^ 1) * 2 * A_PLANE + (size_t)arow * AP + acolb;
            __nv_bfloat16* dl = dh + A_PLANE;
#pragma unroll
            for (int half4 = 0; half4 < 2; half4++) {
                float4 v = half4 ? pre1 : pre0;
                __nv_bfloat16 h0 = __float2bfloat16(v.x), h1 = __float2bfloat16(v.y);
                __nv_bfloat16 h2 = __float2bfloat16(v.z), h3 = __float2bfloat16(v.w);
                __nv_bfloat16 l0 = __float2bfloat16(v.x - __bfloat162float(h0));
                __nv_bfloat16 l1 = __float2bfloat16(v.y - __bfloat162float(h1));
                __nv_bfloat16 l2 = __float2bfloat16(v.z - __bfloat162float(h2));
                __nv_bfloat16 l3 = __float2bfloat16(v.w - __bfloat162float(h3));
                *(uint2*)(dh + half4 * 4) = make_uint2(pack2(h0, h1), pack2(h2, h3));
                *(uint2*)(dl + half4 * 4) = make_uint2(pack2(l0, l1), pack2(l2, l3));
            }
            CP_WAIT0();
        }
        __syncthreads();
    }

    // ---- epilogue: relu(acc * sc[n] + ctab[seg[m], n]) ----
    int r0 = lane >> 2;
    int cq = (lane & 3) * 2;
#pragma unroll
    for (int ms = 0; ms < 4; ms++) {
        int row = m0 + wm * 64 + ms * 16 + r0;
        int s0 = 0, s1 = 0;
        while (row >= so_s[s0]) s0++;
        while (row + 8 >= so_s[s1]) s1++;
        const float* ct0 = g_ctab + s0 * C;
        const float* ct1 = g_ctab + s1 * C;
        float* o0 = out + (size_t)row * C;
        float* o1 = out + (size_t)(row + 8) * C;
#pragma unroll
        for (int ns = 0; ns < 4; ns++) {
            int col = wn * 32 + ns * 8 + cq;
            float2 sc2 = *(const float2*)&g_scale[col];
            float2 ca = *(const float2*)&ct0[col];
            float2 cb = *(const float2*)&ct1[col];
            float2 va, vb;
            va.x = fmaxf(fmaf(acc[ms][ns][0], sc2.x, ca.x), 0.0f);
            va.y = fmaxf(fmaf(acc[ms][ns][1], sc2.y, ca.y), 0.0f);
            vb.x = fmaxf(fmaf(acc[ms][ns][2], sc2.x, cb.x), 0.0f);
            vb.y = fmaxf(fmaf(acc[ms][ns][3], sc2.y, cb.y), 0.0f);
            *(float2*)&o0[col] = va;
            *(float2*)&o1[col] = vb;
        }
    }
}

// ---------------------------------------------------------------------------
extern "C" void kernel_launch(void* const* d_in, const int* in_sizes, int n_in,
                              void* d_out, int out_size) {
    const float* x     = (const float*)d_in[0];
    const int*   o     = (const int*)d_in[1];
    const float* W2    = (const float*)d_in[2];
    const float* b2    = (const float*)d_in[3];
    const float* W1    = (const float*)d_in[4];
    const float* b1    = (const float*)d_in[5];
    const float* gamma = (const float*)d_in[6];
    const float* beta  = (const float*)d_in[7];
    const float* rm    = (const float*)d_in[8];
    const float* rv    = (const float*)d_in[9];
    float* out = (float*)d_out;

    cudaFuncSetAttribute(k3_mma, cudaFuncAttributeMaxDynamicSharedMemorySize, K3_SMEM);

    k0_zero<<<16, 256>>>();
    kw_split<<<256, 256>>>(W1);
    k1_segsum<<<NROWS / 128, 256>>>(x, o);
    k2_tiny<<<S, 256>>>(o, W2, b2, W1, b1, gamma, beta, rm, rv);
    k3_mma<<<NROWS / BM, NT, K3_SMEM>>>(x, o, out);
}

// round 5
// speedup vs baseline: 2.9993x; 1.6352x over previous
#include <cuda_runtime.h>
#include <cuda_fp16.h>
#include <cstdint>
#include <math.h>

#define NROWS 262144
#define C 256
#define S 16

#define BM 128
#define BK 64
#define NCHUNK 4          // K=256 / BK
#define NT 512            // threads per CTA
#define AP 72             // A smem row stride in halves (64 + 8 pad)
#define BP 264            // B smem row stride in halves (256 + 8 pad)

// ---------------- scratch ---------------------------------------------------
__device__ float g_segsum[S * C];
__device__ float g_h[S * C];        // relu(mean@W2 + b2)
__device__ float g_ctab[S * C];     // (h@W1b + b1)*sc + beta - rm*sc
// B image: [chunk][k=64][BP] fp16 of (W1a * diag(bn_scale)), exact smem layout
__device__ __half g_Bimg[NCHUNK * BK * BP];

// ---------------- helpers ---------------------------------------------------
__device__ __forceinline__ uint32_t smem_u32(const void* p) {
    uint32_t a;
    asm("{ .reg .u64 t; cvta.to.shared.u64 t, %1; cvt.u32.u64 %0, t; }" : "=r"(a) : "l"(p));
    return a;
}
#define CP_ASYNC16(dst, src) asm volatile("cp.async.cg.shared.global [%0], [%1], 16;" :: "r"(dst), "l"(src))
#define CP_COMMIT() asm volatile("cp.async.commit_group;" ::: "memory")
#define CP_WAIT0()  asm volatile("cp.async.wait_group 0;" ::: "memory")

#define LDSM_X4(r0, r1, r2, r3, addr) \
    asm volatile("ldmatrix.sync.aligned.m8n8.x4.shared.b16 {%0,%1,%2,%3}, [%4];" \
                 : "=r"(r0), "=r"(r1), "=r"(r2), "=r"(r3) : "r"(addr))
#define LDSM_X2_T(r0, r1, addr) \
    asm volatile("ldmatrix.sync.aligned.m8n8.x2.trans.shared.b16 {%0,%1}, [%2];" \
                 : "=r"(r0), "=r"(r1) : "r"(addr))

#define MMA_F16(d, a, b) \
    asm volatile("mma.sync.aligned.m16n8k16.row.col.f32.f16.f16.f32 " \
                 "{%0,%1,%2,%3}, {%4,%5,%6,%7}, {%8,%9}, {%0,%1,%2,%3};" \
                 : "+f"((d)[0]), "+f"((d)[1]), "+f"((d)[2]), "+f"((d)[3]) \
                 : "r"((a)[0]), "r"((a)[1]), "r"((a)[2]), "r"((a)[3]), "r"((b)[0]), "r"((b)[1]))

// ---------------------------------------------------------------------------
__global__ void k0_zero() {
    int i = blockIdx.x * blockDim.x + threadIdx.x;
    if (i < S * C) g_segsum[i] = 0.0f;
}

// W1a rows (k=0..255) scaled by bn scale per column, fp16, chunk images
__global__ void kw_split(const float* __restrict__ W1,
                         const float* __restrict__ gamma,
                         const float* __restrict__ rv) {
    int k = blockIdx.x;   // 0..255
    int n = threadIdx.x;  // 0..255
    float sc = gamma[n] * rsqrtf(rv[n] + 1e-5f);
    float w = W1[k * C + n] * sc;
    int c = k >> 6, kk = k & 63;
    g_Bimg[(c * BK + kk) * BP + n] = __float2half_rn(w);
    if (n < BP - 256)
        g_Bimg[(c * BK + kk) * BP + 256 + n] = __float2half_rn(0.0f);
}

// segment sums
__global__ void __launch_bounds__(256) k1_segsum(const float* __restrict__ x,
                                                 const int* __restrict__ o32) {
    __shared__ int so[S];
    if (threadIdx.x < S) {
        int stride = (o32[1] == 0) ? 2 : 1;
        so[threadIdx.x] = o32[threadIdx.x * stride];
    }
    __syncthreads();
    int t = threadIdx.x;
    int g0 = blockIdx.x * 128;
    int s = 0;
    while (g0 >= so[s]) s++;
    int r = 0;
    while (r < 128) {
        int end = so[s] - g0;
        if (end > 128) end = 128;
        float acc = 0.0f;
        for (; r + 4 <= end; r += 4) {
            acc += __ldg(&x[(size_t)(g0 + r + 0) * C + t]) + __ldg(&x[(size_t)(g0 + r + 1) * C + t]) +
                   __ldg(&x[(size_t)(g0 + r + 2) * C + t]) + __ldg(&x[(size_t)(g0 + r + 3) * C + t]);
        }
        for (; r < end; r++) acc += __ldg(&x[(size_t)(g0 + r) * C + t]);
        atomicAdd(&g_segsum[s * C + t], acc);
        s++;
    }
}

// k2a: h[s, col] = relu(mean[s] @ W2 + b2), grid = S*8, block 256 (32 cols x 8 k-groups)
__global__ void __launch_bounds__(256) k2a(const int* __restrict__ o32,
                                           const float* __restrict__ W2,
                                           const float* __restrict__ b2) {
    __shared__ float mean_s[C];
    __shared__ float red[256];
    int s = blockIdx.x >> 3, g = blockIdx.x & 7;
    int tid = threadIdx.x;
    int stride = (o32[1] == 0) ? 2 : 1;
    int oe = o32[s * stride];
    int ob = (s > 0) ? o32[(s - 1) * stride] : 0;
    float inv = 1.0f / (float)(oe - ob);
    mean_s[tid] = g_segsum[s * C + tid] * inv;
    __syncthreads();
    int col = g * 32 + (tid & 31);
    int kc = tid >> 5;
    float acc = 0.0f;
#pragma unroll 8
    for (int i = 0; i < 32; i++)
        acc = fmaf(mean_s[kc * 32 + i], __ldg(&W2[(size_t)(kc * 32 + i) * C + col]), acc);
    red[tid] = acc;
    __syncthreads();
    if (tid < 32) {
        float t = red[tid];
#pragma unroll
        for (int j = 1; j < 8; j++) t += red[j * 32 + tid];
        int c0 = g * 32 + tid;
        g_h[s * C + c0] = fmaxf(t + __ldg(&b2[c0]), 0.0f);
    }
}

// k2b: ctab[s, col] = (h[s]@W1b + b1)*sc + beta - rm*sc
__global__ void __launch_bounds__(256) k2b(const float* __restrict__ W1,
                                           const float* __restrict__ b1,
                                           const float* __restrict__ gamma,
                                           const float* __restrict__ beta,
                                           const float* __restrict__ rm,
                                           const float* __restrict__ rv) {
    __shared__ float h_s[C];
    __shared__ float red[256];
    int s = blockIdx.x >> 3, g = blockIdx.x & 3;  // note: grid = S*4? keep 8
    g = blockIdx.x & 7;
    int tid = threadIdx.x;
    h_s[tid] = g_h[s * C + tid];
    __syncthreads();
    int col = g * 32 + (tid & 31);
    int kc = tid >> 5;
    float acc = 0.0f;
#pragma unroll 8
    for (int i = 0; i < 32; i++)
        acc = fmaf(h_s[kc * 32 + i], __ldg(&W1[(size_t)(C + kc * 32 + i) * C + col]), acc);
    red[tid] = acc;
    __syncthreads();
    if (tid < 32) {
        float t = red[tid];
#pragma unroll
        for (int j = 1; j < 8; j++) t += red[j * 32 + tid];
        int c0 = g * 32 + tid;
        float sc = gamma[c0] * rsqrtf(rv[c0] + 1e-5f);
        g_ctab[s * C + c0] = (t + __ldg(&b1[c0])) * sc + beta[c0] - rm[c0] * sc;
    }
}

// ---------------------------------------------------------------------------
// k3: fp16 mma.sync GEMM (single term, BN scale folded into B) + fused epilogue
// smem: [so 128B][A: 2 buf x 128 x AP halves][B: 2 buf x 64 x BP halves]
// ---------------------------------------------------------------------------
#define A_BYTES (BM * AP * 2)     // 18432
#define B_BYTES (BK * BP * 2)     // 33792
#define A_OFF 128
#define B_OFF (A_OFF + 2 * A_BYTES)
#define K3_SMEM (B_OFF + 2 * B_BYTES)

__global__ void __launch_bounds__(NT, 1) k3_mma(const float* __restrict__ x,
                                                const int* __restrict__ o32,
                                                float* __restrict__ out) {
    extern __shared__ char smem[];
    uint32_t sbase = smem_u32(smem);
    int* so_s = (int*)smem;
    __half* Asm = (__half*)(smem + A_OFF);
    const uint32_t aA = sbase + A_OFF;
    const uint32_t aB = sbase + B_OFF;

    int tid = threadIdx.x;
    int lane = tid & 31;
    int wid = tid >> 5;
    int wm = wid >> 3;   // 0..1
    int wn = wid & 7;    // 0..7
    int m0 = blockIdx.x * BM;

    if (tid < S) {
        int stride = (o32[1] == 0) ? 2 : 1;
        so_s[tid] = o32[tid * stride];
    }

    // A load geometry: 4 threads per row, 16 consecutive floats each
    int arow = tid >> 2;
    int acol = (tid & 3) * 16;
    const float* agp = x + (size_t)(m0 + arow) * C + acol;

    float acc[4][4][4];
#pragma unroll
    for (int i = 0; i < 4; i++)
#pragma unroll
        for (int j = 0; j < 4; j++)
#pragma unroll
            for (int r = 0; r < 4; r++) acc[i][j][r] = 0.0f;

    uint32_t aoff[4];
#pragma unroll
    for (int ms = 0; ms < 4; ms++)
        aoff[ms] = (uint32_t)(((wm * 64 + ms * 16 + (lane & 15)) * AP + ((lane >> 4) << 3)) * 2);
    uint32_t boff[4];
#pragma unroll
    for (int ns = 0; ns < 4; ns++)
        boff[ns] = (uint32_t)(((lane & 15) * BP + wn * 32 + ns * 8) * 2);

    float4 pre[4];

    // ---- prologue: chunk 0 ----
#pragma unroll
    for (int j = 0; j < 4; j++) pre[j] = __ldg((const float4*)(agp + j * 4));
    {
        const char* src = (const char*)g_Bimg;
        for (int i = tid; i < B_BYTES / 16; i += NT)
            CP_ASYNC16(aB + (uint32_t)(i * 16), src + i * 16);
        CP_COMMIT();
    }
    {
        __half* dst = Asm + (size_t)arow * AP + acol;
#pragma unroll
        for (int j = 0; j < 4; j++) {
            __half2 a = __float22half2_rn(make_float2(pre[j].x, pre[j].y));
            __half2 b = __float22half2_rn(make_float2(pre[j].z, pre[j].w));
            *(uint2*)(dst + j * 4) = make_uint2(*(uint32_t*)&a, *(uint32_t*)&b);
        }
    }
    CP_WAIT0();
    __syncthreads();

#pragma unroll 1
    for (int c = 0; c < NCHUNK; c++) {
        int buf = c & 1;
        uint32_t abuf = aA + (uint32_t)(buf * A_BYTES);
        uint32_t bbuf = aB + (uint32_t)(buf * B_BYTES);

        if (c < NCHUNK - 1) {
#pragma unroll
            for (int j = 0; j < 4; j++)
                pre[j] = __ldg((const float4*)(agp + (c + 1) * BK + j * 4));
            const char* src = (const char*)(g_Bimg + (size_t)(c + 1) * BK * BP);
            uint32_t dst = aB + (uint32_t)((buf ^ 1) * B_BYTES);
            for (int i = tid; i < B_BYTES / 16; i += NT)
                CP_ASYNC16(dst + (uint32_t)(i * 16), src + i * 16);
            CP_COMMIT();
        }

        // ---- compute chunk c: kk = 0,16,32,48 ----
#pragma unroll
        for (int kk = 0; kk < BK; kk += 16) {
            uint32_t bf[4][2];
#pragma unroll
            for (int ns = 0; ns < 4; ns++)
                LDSM_X2_T(bf[ns][0], bf[ns][1], bbuf + boff[ns] + (uint32_t)(kk * BP * 2));
#pragma unroll
            for (int ms = 0; ms < 4; ms++) {
                uint32_t af[4];
                LDSM_X4(af[0], af[1], af[2], af[3], abuf + aoff[ms] + (uint32_t)(kk * 2));
#pragma unroll
                for (int ns = 0; ns < 4; ns++) MMA_F16(acc[ms][ns], af, bf[ns]);
            }
        }

        if (c < NCHUNK - 1) {
            __half* dst = Asm + (size_t)(buf ^ 1) * (A_BYTES / 2) + (size_t)arow * AP + acol;
#pragma unroll
            for (int j = 0; j < 4; j++) {
                __half2 a = __float22half2_rn(make_float2(pre[j].x, pre[j].y));
                __half2 b = __float22half2_rn(make_float2(pre[j].z, pre[j].w));
                *(uint2*)(dst + j * 4) = make_uint2(*(uint32_t*)&a, *(uint32_t*)&b);
            }
            CP_WAIT0();
            __syncthreads();
        }
    }

    // ---- epilogue: relu(acc + ctab[seg]) ----
    int r0 = lane >> 2;
    int cq = (lane & 3) * 2;
#pragma unroll
    for (int ms = 0; ms < 4; ms++) {
        int row = m0 + wm * 64 + ms * 16 + r0;
        int s0 = 0, s1 = 0;
        while (row >= so_s[s0]) s0++;
        while (row + 8 >= so_s[s1]) s1++;
        const float* ct0 = g_ctab + s0 * C;
        const float* ct1 = g_ctab + s1 * C;
        float* o0 = out + (size_t)row * C;
        float* o1 = out + (size_t)(row + 8) * C;
#pragma unroll
        for (int ns = 0; ns < 4; ns++) {
            int col = wn * 32 + ns * 8 + cq;
            float2 ca = *(const float2*)&ct0[col];
            float2 cb = *(const float2*)&ct1[col];
            float2 va, vb;
            va.x = fmaxf(acc[ms][ns][0] + ca.x, 0.0f);
            va.y = fmaxf(acc[ms][ns][1] + ca.y, 0.0f);
            vb.x = fmaxf(acc[ms][ns][2] + cb.x, 0.0f);
            vb.y = fmaxf(acc[ms][ns][3] + cb.y, 0.0f);
            *(float2*)&o0[col] = va;
            *(float2*)&o1[col] = vb;
        }
    }
}

// ---------------------------------------------------------------------------
extern "C" void kernel_launch(void* const* d_in, const int* in_sizes, int n_in,
                              void* d_out, int out_size) {
    const float* x     = (const float*)d_in[0];
    const int*   o     = (const int*)d_in[1];
    const float* W2    = (const float*)d_in[2];
    const float* b2    = (const float*)d_in[3];
    const float* W1    = (const float*)d_in[4];
    const float* b1    = (const float*)d_in[5];
    const float* gamma = (const float*)d_in[6];
    const float* beta  = (const float*)d_in[7];
    const float* rm    = (const float*)d_in[8];
    const float* rv    = (const float*)d_in[9];
    float* out = (float*)d_out;

    cudaFuncSetAttribute(k3_mma, cudaFuncAttributeMaxDynamicSharedMemorySize, K3_SMEM);

    k0_zero<<<16, 256>>>();
    kw_split<<<256, 256>>>(W1, gamma, rv);
    k1_segsum<<<NROWS / 128, 256>>>(x, o);
    k2a<<<S * 8, 256>>>(o, W2, b2);
    k2b<<<S * 8, 256>>>(W1, b1, gamma, beta, rm, rv);
    k3_mma<<<NROWS / BM, NT, K3_SMEM>>>(x, o, out);
}

// round 6
// speedup vs baseline: 3.2134x; 1.0714x over previous
#include <cuda_runtime.h>
#include <cuda_fp16.h>
#include <cstdint>
#include <math.h>

#define NROWS 262144
#define C 256
#define S 16

#define BM 64
#define BK 64
#define NCHUNK 4          // K=256 / BK
#define NT 256            // threads per CTA
#define AP 72             // A smem row stride in halves (64 + 8 pad) -> 144B, conflict-free
#define BP 264            // B smem row stride in halves (256 + 8 pad) -> 528B, conflict-free

// ---------------- scratch ---------------------------------------------------
__device__ float g_segsum[S * C];
__device__ float g_h[S * C];        // relu(mean@W2 + b2)
__device__ float g_ctab[S * C];     // (h@W1b + b1)*sc + beta - rm*sc
// B image: [chunk][k=64][BP] fp16 of (W1a * diag(bn_scale)), exact smem layout
__device__ __half g_Bimg[NCHUNK * BK * BP];

// ---------------- helpers ---------------------------------------------------
__device__ __forceinline__ uint32_t smem_u32(const void* p) {
    uint32_t a;
    asm("{ .reg .u64 t; cvta.to.shared.u64 t, %1; cvt.u32.u64 %0, t; }" : "=r"(a) : "l"(p));
    return a;
}
#define CP_ASYNC16(dst, src) asm volatile("cp.async.cg.shared.global [%0], [%1], 16;" :: "r"(dst), "l"(src))
#define CP_COMMIT() asm volatile("cp.async.commit_group;" ::: "memory")
#define CP_WAIT0()  asm volatile("cp.async.wait_group 0;" ::: "memory")

#define LDSM_X4(r0, r1, r2, r3, addr) \
    asm volatile("ldmatrix.sync.aligned.m8n8.x4.shared.b16 {%0,%1,%2,%3}, [%4];" \
                 : "=r"(r0), "=r"(r1), "=r"(r2), "=r"(r3) : "r"(addr))
#define LDSM_X2_T(r0, r1, addr) \
    asm volatile("ldmatrix.sync.aligned.m8n8.x2.trans.shared.b16 {%0,%1}, [%2];" \
                 : "=r"(r0), "=r"(r1) : "r"(addr))

#define MMA_F16(d, a, b) \
    asm volatile("mma.sync.aligned.m16n8k16.row.col.f32.f16.f16.f32 " \
                 "{%0,%1,%2,%3}, {%4,%5,%6,%7}, {%8,%9}, {%0,%1,%2,%3};" \
                 : "+f"((d)[0]), "+f"((d)[1]), "+f"((d)[2]), "+f"((d)[3]) \
                 : "r"((a)[0]), "r"((a)[1]), "r"((a)[2]), "r"((a)[3]), "r"((b)[0]), "r"((b)[1]))

// ---------------------------------------------------------------------------
// kw: W1a rows scaled by BN scale per column, fp16 chunk images; also zeros segsum
__global__ void kw_split(const float* __restrict__ W1,
                         const float* __restrict__ gamma,
                         const float* __restrict__ rv) {
    int k = blockIdx.x;   // 0..255
    int n = threadIdx.x;  // 0..255
    if (k < S) g_segsum[k * C + n] = 0.0f;
    float sc = gamma[n] * rsqrtf(rv[n] + 1e-5f);
    float w = W1[k * C + n] * sc;
    int c = k >> 6, kk = k & 63;
    g_Bimg[(c * BK + kk) * BP + n] = __float2half_rn(w);
    if (n < BP - 256)
        g_Bimg[(c * BK + kk) * BP + 256 + n] = __float2half_rn(0.0f);
}

// segment sums
__global__ void __launch_bounds__(256) k1_segsum(const float* __restrict__ x,
                                                 const int* __restrict__ o32) {
    __shared__ int so[S];
    if (threadIdx.x < S) {
        int stride = (o32[1] == 0) ? 2 : 1;
        so[threadIdx.x] = o32[threadIdx.x * stride];
    }
    __syncthreads();
    int t = threadIdx.x;
    int g0 = blockIdx.x * 128;
    int s = 0;
    while (g0 >= so[s]) s++;
    int r = 0;
    while (r < 128) {
        int end = so[s] - g0;
        if (end > 128) end = 128;
        float acc = 0.0f;
        for (; r + 4 <= end; r += 4) {
            acc += __ldg(&x[(size_t)(g0 + r + 0) * C + t]) + __ldg(&x[(size_t)(g0 + r + 1) * C + t]) +
                   __ldg(&x[(size_t)(g0 + r + 2) * C + t]) + __ldg(&x[(size_t)(g0 + r + 3) * C + t]);
        }
        for (; r < end; r++) acc += __ldg(&x[(size_t)(g0 + r) * C + t]);
        atomicAdd(&g_segsum[s * C + t], acc);
        s++;
    }
}

// k2a: h[s, col] = relu(mean[s] @ W2 + b2), grid = S*8
__global__ void __launch_bounds__(256) k2a(const int* __restrict__ o32,
                                           const float* __restrict__ W2,
                                           const float* __restrict__ b2) {
    __shared__ float mean_s[C];
    __shared__ float red[256];
    int s = blockIdx.x >> 3, g = blockIdx.x & 7;
    int tid = threadIdx.x;
    int stride = (o32[1] == 0) ? 2 : 1;
    int oe = o32[s * stride];
    int ob = (s > 0) ? o32[(s - 1) * stride] : 0;
    float inv = 1.0f / (float)(oe - ob);
    mean_s[tid] = g_segsum[s * C + tid] * inv;
    __syncthreads();
    int col = g * 32 + (tid & 31);
    int kc = tid >> 5;
    float acc = 0.0f;
#pragma unroll 8
    for (int i = 0; i < 32; i++)
        acc = fmaf(mean_s[kc * 32 + i], __ldg(&W2[(size_t)(kc * 32 + i) * C + col]), acc);
    red[tid] = acc;
    __syncthreads();
    if (tid < 32) {
        float t = red[tid];
#pragma unroll
        for (int j = 1; j < 8; j++) t += red[j * 32 + tid];
        int c0 = g * 32 + tid;
        g_h[s * C + c0] = fmaxf(t + __ldg(&b2[c0]), 0.0f);
    }
}

// k2b: ctab[s, col] = (h[s]@W1b + b1)*sc + beta - rm*sc
__global__ void __launch_bounds__(256) k2b(const float* __restrict__ W1,
                                           const float* __restrict__ b1,
                                           const float* __restrict__ gamma,
                                           const float* __restrict__ beta,
                                           const float* __restrict__ rm,
                                           const float* __restrict__ rv) {
    __shared__ float h_s[C];
    __shared__ float red[256];
    int s = blockIdx.x >> 3;
    int g = blockIdx.x & 7;
    int tid = threadIdx.x;
    h_s[tid] = g_h[s * C + tid];
    __syncthreads();
    int col = g * 32 + (tid & 31);
    int kc = tid >> 5;
    float acc = 0.0f;
#pragma unroll 8
    for (int i = 0; i < 32; i++)
        acc = fmaf(h_s[kc * 32 + i], __ldg(&W1[(size_t)(C + kc * 32 + i) * C + col]), acc);
    red[tid] = acc;
    __syncthreads();
    if (tid < 32) {
        float t = red[tid];
#pragma unroll
        for (int j = 1; j < 8; j++) t += red[j * 32 + tid];
        int c0 = g * 32 + tid;
        float sc = gamma[c0] * rsqrtf(rv[c0] + 1e-5f);
        g_ctab[s * C + c0] = (t + __ldg(&b1[c0])) * sc + beta[c0] - rm[c0] * sc;
    }
}

// ---------------------------------------------------------------------------
// k3: fp16 mma.sync GEMM, BM=64 x BN=256 per CTA, 256 threads, 2 CTAs/SM.
// smem: [so 128B][A: 2 buf x 64 x AP halves][B: 2 buf x 64 x BP halves]
// ---------------------------------------------------------------------------
#define A_BYTES (BM * AP * 2)     // 9216
#define B_BYTES (BK * BP * 2)     // 33792
#define A_OFF 128
#define B_OFF (A_OFF + 2 * A_BYTES)
#define K3_SMEM (B_OFF + 2 * B_BYTES)

__global__ void __launch_bounds__(NT, 2) k3_mma(const float* __restrict__ x,
                                                const int* __restrict__ o32,
                                                float* __restrict__ out) {
    extern __shared__ char smem[];
    uint32_t sbase = smem_u32(smem);
    int* so_s = (int*)smem;
    __half* Asm = (__half*)(smem + A_OFF);
    const uint32_t aA = sbase + A_OFF;
    const uint32_t aB = sbase + B_OFF;

    int tid = threadIdx.x;
    int lane = tid & 31;
    int wn = tid >> 5;   // 0..7 : warp = 64 rows x 32 cols
    int m0 = blockIdx.x * BM;

    if (tid < S) {
        int stride = (o32[1] == 0) ? 2 : 1;
        so_s[tid] = o32[tid * stride];
    }

    // A load geometry: 4 threads per row, 16 consecutive floats each
    int arow = tid >> 2;         // 0..63
    int acol = (tid & 3) * 16;   // 0,16,32,48
    const float* agp = x + (size_t)(m0 + arow) * C + acol;

    float acc[4][4][4];
#pragma unroll
    for (int i = 0; i < 4; i++)
#pragma unroll
        for (int j = 0; j < 4; j++)
#pragma unroll
            for (int r = 0; r < 4; r++) acc[i][j][r] = 0.0f;

    uint32_t aoff[4];
#pragma unroll
    for (int ms = 0; ms < 4; ms++)
        aoff[ms] = (uint32_t)(((ms * 16 + (lane & 15)) * AP + ((lane >> 4) << 3)) * 2);
    uint32_t boff[4];
#pragma unroll
    for (int ns = 0; ns < 4; ns++)
        boff[ns] = (uint32_t)(((lane & 15) * BP + wn * 32 + ns * 8) * 2);

    float4 pre[4];

    // ---- prologue: chunk 0 ----
#pragma unroll
    for (int j = 0; j < 4; j++) pre[j] = __ldg((const float4*)(agp + j * 4));
    {
        const char* src = (const char*)g_Bimg;
        for (int i = tid; i < B_BYTES / 16; i += NT)
            CP_ASYNC16(aB + (uint32_t)(i * 16), src + i * 16);
        CP_COMMIT();
    }
    {
        __half* dst = Asm + (size_t)arow * AP + acol;
#pragma unroll
        for (int j = 0; j < 4; j++) {
            __half2 a = __float22half2_rn(make_float2(pre[j].x, pre[j].y));
            __half2 b = __float22half2_rn(make_float2(pre[j].z, pre[j].w));
            *(uint2*)(dst + j * 4) = make_uint2(*(uint32_t*)&a, *(uint32_t*)&b);
        }
    }
    CP_WAIT0();
    __syncthreads();

#pragma unroll 1
    for (int c = 0; c < NCHUNK; c++) {
        int buf = c & 1;
        uint32_t abuf = aA + (uint32_t)(buf * A_BYTES);
        uint32_t bbuf = aB + (uint32_t)(buf * B_BYTES);

        if (c < NCHUNK - 1) {
#pragma unroll
            for (int j = 0; j < 4; j++)
                pre[j] = __ldg((const float4*)(agp + (c + 1) * BK + j * 4));
            const char* src = (const char*)(g_Bimg + (size_t)(c + 1) * BK * BP);
            uint32_t dst = aB + (uint32_t)((buf ^ 1) * B_BYTES);
            for (int i = tid; i < B_BYTES / 16; i += NT)
                CP_ASYNC16(dst + (uint32_t)(i * 16), src + i * 16);
            CP_COMMIT();
        }

        // ---- compute chunk c: kk = 0,16,32,48 ----
#pragma unroll
        for (int kk = 0; kk < BK; kk += 16) {
            uint32_t bf[4][2];
#pragma unroll
            for (int ns = 0; ns < 4; ns++)
                LDSM_X2_T(bf[ns][0], bf[ns][1], bbuf + boff[ns] + (uint32_t)(kk * BP * 2));
#pragma unroll
            for (int ms = 0; ms < 4; ms++) {
                uint32_t af[4];
                LDSM_X4(af[0], af[1], af[2], af[3], abuf + aoff[ms] + (uint32_t)(kk * 2));
#pragma unroll
                for (int ns = 0; ns < 4; ns++) MMA_F16(acc[ms][ns], af, bf[ns]);
            }
        }

        if (c < NCHUNK - 1) {
            __half* dst = Asm + (size_t)(buf ^ 1) * (A_BYTES / 2) + (size_t)arow * AP + acol;
#pragma unroll
            for (int j = 0; j < 4; j++) {
                __half2 a = __float22half2_rn(make_float2(pre[j].x, pre[j].y));
                __half2 b = __float22half2_rn(make_float2(pre[j].z, pre[j].w));
                *(uint2*)(dst + j * 4) = make_uint2(*(uint32_t*)&a, *(uint32_t*)&b);
            }
            CP_WAIT0();
            __syncthreads();
        }
    }

    // ---- epilogue: relu(acc + ctab[seg]) ----
    int r0 = lane >> 2;
    int cq = (lane & 3) * 2;
#pragma unroll
    for (int ms = 0; ms < 4; ms++) {
        int row = m0 + ms * 16 + r0;
        int s0 = 0, s1 = 0;
        while (row >= so_s[s0]) s0++;
        while (row + 8 >= so_s[s1]) s1++;
        const float* ct0 = g_ctab + s0 * C;
        const float* ct1 = g_ctab + s1 * C;
        float* o0 = out + (size_t)row * C;
        float* o1 = out + (size_t)(row + 8) * C;
#pragma unroll
        for (int ns = 0; ns < 4; ns++) {
            int col = wn * 32 + ns * 8 + cq;
            float2 ca = *(const float2*)&ct0[col];
            float2 cb = *(const float2*)&ct1[col];
            float2 va, vb;
            va.x = fmaxf(acc[ms][ns][0] + ca.x, 0.0f);
            va.y = fmaxf(acc[ms][ns][1] + ca.y, 0.0f);
            vb.x = fmaxf(acc[ms][ns][2] + cb.x, 0.0f);
            vb.y = fmaxf(acc[ms][ns][3] + cb.y, 0.0f);
            *(float2*)&o0[col] = va;
            *(float2*)&o1[col] = vb;
        }
    }
}

// ---------------------------------------------------------------------------
extern "C" void kernel_launch(void* const* d_in, const int* in_sizes, int n_in,
                              void* d_out, int out_size) {
    const float* x     = (const float*)d_in[0];
    const int*   o     = (const int*)d_in[1];
    const float* W2    = (const float*)d_in[2];
    const float* b2    = (const float*)d_in[3];
    const float* W1    = (const float*)d_in[4];
    const float* b1    = (const float*)d_in[5];
    const float* gamma = (const float*)d_in[6];
    const float* beta  = (const float*)d_in[7];
    const float* rm    = (const float*)d_in[8];
    const float* rv    = (const float*)d_in[9];
    float* out = (float*)d_out;

    cudaFuncSetAttribute(k3_mma, cudaFuncAttributeMaxDynamicSharedMemorySize, K3_SMEM);

    kw_split<<<256, 256>>>(W1, gamma, rv);
    k1_segsum<<<NROWS / 128, 256>>>(x, o);
    k2a<<<S * 8, 256>>>(o, W2, b2);
    k2b<<<S * 8, 256>>>(W1, b1, gamma, beta, rm, rv);
    k3_mma<<<NROWS / BM, NT, K3_SMEM>>>(x, o, out);
}

// round 7
// speedup vs baseline: 3.2974x; 1.0261x over previous
#include <cuda_runtime.h>
#include <cuda_fp16.h>
#include <cstdint>
#include <math.h>

#define NROWS 262144
#define C 256
#define S 16

#define BM 128
#define BK 64
#define NCHUNK 4          // K=256 / BK
#define NT 512            // threads per CTA
#define NTILE (NROWS / BM)  // 2048
#define GRID 148
#define AP 72             // A smem row stride in halves (64 + 8 pad)
#define BP 264            // B smem row stride in halves (256 + 8 pad)

// ---------------- scratch ---------------------------------------------------
__device__ float g_segsum[S * C];
__device__ float g_h[S * C];
__device__ float g_ctab[S * C];
// B image: [chunk][k=64][BP] fp16 of (W1a * diag(bn_scale)), exact smem layout
__device__ __half g_Bimg[NCHUNK * BK * BP];

// ---------------- helpers ---------------------------------------------------
__device__ __forceinline__ uint32_t smem_u32(const void* p) {
    uint32_t a;
    asm("{ .reg .u64 t; cvta.to.shared.u64 t, %1; cvt.u32.u64 %0, t; }" : "=r"(a) : "l"(p));
    return a;
}
#define CP_ASYNC16(dst, src) asm volatile("cp.async.cg.shared.global [%0], [%1], 16;" :: "r"(dst), "l"(src))
#define CP_COMMIT() asm volatile("cp.async.commit_group;" ::: "memory")
#define CP_WAIT0()  asm volatile("cp.async.wait_group 0;" ::: "memory")

#define LDSM_X4(r0, r1, r2, r3, addr) \
    asm volatile("ldmatrix.sync.aligned.m8n8.x4.shared.b16 {%0,%1,%2,%3}, [%4];" \
                 : "=r"(r0), "=r"(r1), "=r"(r2), "=r"(r3) : "r"(addr))
#define LDSM_X2_T(r0, r1, addr) \
    asm volatile("ldmatrix.sync.aligned.m8n8.x2.trans.shared.b16 {%0,%1}, [%2];" \
                 : "=r"(r0), "=r"(r1) : "r"(addr))

#define MMA_F16(d, a, b) \
    asm volatile("mma.sync.aligned.m16n8k16.row.col.f32.f16.f16.f32 " \
                 "{%0,%1,%2,%3}, {%4,%5,%6,%7}, {%8,%9}, {%0,%1,%2,%3};" \
                 : "+f"((d)[0]), "+f"((d)[1]), "+f"((d)[2]), "+f"((d)[3]) \
                 : "r"((a)[0]), "r"((a)[1]), "r"((a)[2]), "r"((a)[3]), "r"((b)[0]), "r"((b)[1]))

// ---------------------------------------------------------------------------
// kw: W1a rows scaled by BN scale per column, fp16 chunk images; zeros segsum
__global__ void kw_split(const float* __restrict__ W1,
                         const float* __restrict__ gamma,
                         const float* __restrict__ rv) {
    int k = blockIdx.x;   // 0..255
    int n = threadIdx.x;  // 0..255
    if (k < S) g_segsum[k * C + n] = 0.0f;
    float sc = gamma[n] * rsqrtf(rv[n] + 1e-5f);
    float w = W1[k * C + n] * sc;
    int c = k >> 6, kk = k & 63;
    g_Bimg[(c * BK + kk) * BP + n] = __float2half_rn(w);
    if (n < BP - 256)
        g_Bimg[(c * BK + kk) * BP + 256 + n] = __float2half_rn(0.0f);
}

// segment sums
__global__ void __launch_bounds__(256) k1_segsum(const float* __restrict__ x,
                                                 const int* __restrict__ o32) {
    __shared__ int so[S];
    if (threadIdx.x < S) {
        int stride = (o32[1] == 0) ? 2 : 1;
        so[threadIdx.x] = o32[threadIdx.x * stride];
    }
    __syncthreads();
    int t = threadIdx.x;
    int g0 = blockIdx.x * 128;
    int s = 0;
    while (g0 >= so[s]) s++;
    int r = 0;
    while (r < 128) {
        int end = so[s] - g0;
        if (end > 128) end = 128;
        float acc = 0.0f;
        for (; r + 4 <= end; r += 4) {
            acc += __ldg(&x[(size_t)(g0 + r + 0) * C + t]) + __ldg(&x[(size_t)(g0 + r + 1) * C + t]) +
                   __ldg(&x[(size_t)(g0 + r + 2) * C + t]) + __ldg(&x[(size_t)(g0 + r + 3) * C + t]);
        }
        for (; r < end; r++) acc += __ldg(&x[(size_t)(g0 + r) * C + t]);
        atomicAdd(&g_segsum[s * C + t], acc);
        s++;
    }
}

// k2a: h[s, col] = relu(mean[s] @ W2 + b2), grid = S*8
__global__ void __launch_bounds__(256) k2a(const int* __restrict__ o32,
                                           const float* __restrict__ W2,
                                           const float* __restrict__ b2) {
    __shared__ float mean_s[C];
    __shared__ float red[256];
    int s = blockIdx.x >> 3, g = blockIdx.x & 7;
    int tid = threadIdx.x;
    int stride = (o32[1] == 0) ? 2 : 1;
    int oe = o32[s * stride];
    int ob = (s > 0) ? o32[(s - 1) * stride] : 0;
    float inv = 1.0f / (float)(oe - ob);
    mean_s[tid] = g_segsum[s * C + tid] * inv;
    __syncthreads();
    int col = g * 32 + (tid & 31);
    int kc = tid >> 5;
    float acc = 0.0f;
#pragma unroll 8
    for (int i = 0; i < 32; i++)
        acc = fmaf(mean_s[kc * 32 + i], __ldg(&W2[(size_t)(kc * 32 + i) * C + col]), acc);
    red[tid] = acc;
    __syncthreads();
    if (tid < 32) {
        float t = red[tid];
#pragma unroll
        for (int j = 1; j < 8; j++) t += red[j * 32 + tid];
        int c0 = g * 32 + tid;
        g_h[s * C + c0] = fmaxf(t + __ldg(&b2[c0]), 0.0f);
    }
}

// k2b: ctab[s, col] = (h[s]@W1b + b1)*sc + beta - rm*sc
__global__ void __launch_bounds__(256) k2b(const float* __restrict__ W1,
                                           const float* __restrict__ b1,
                                           const float* __restrict__ gamma,
                                           const float* __restrict__ beta,
                                           const float* __restrict__ rm,
                                           const float* __restrict__ rv) {
    __shared__ float h_s[C];
    __shared__ float red[256];
    int s = blockIdx.x >> 3;
    int g = blockIdx.x & 7;
    int tid = threadIdx.x;
    h_s[tid] = g_h[s * C + tid];
    __syncthreads();
    int col = g * 32 + (tid & 31);
    int kc = tid >> 5;
    float acc = 0.0f;
#pragma unroll 8
    for (int i = 0; i < 32; i++)
        acc = fmaf(h_s[kc * 32 + i], __ldg(&W1[(size_t)(C + kc * 32 + i) * C + col]), acc);
    red[tid] = acc;
    __syncthreads();
    if (tid < 32) {
        float t = red[tid];
#pragma unroll
        for (int j = 1; j < 8; j++) t += red[j * 32 + tid];
        int c0 = g * 32 + tid;
        float sc = gamma[c0] * rsqrtf(rv[c0] + 1e-5f);
        g_ctab[s * C + c0] = (t + __ldg(&b1[c0])) * sc + beta[c0] - rm[c0] * sc;
    }
}

// ---------------------------------------------------------------------------
// k3: persistent fp16 mma.sync GEMM. Whole B resident in smem (135 KB);
// each CTA loops over tiles (stride GRID), double-buffered A, flat
// (tile,chunk) software pipeline.
// smem: [so 128B][A: 2 buf x 128 x AP halves][B: 4 chunk x 64 x BP halves]
// ---------------------------------------------------------------------------
#define A_BYTES (BM * AP * 2)       // 18432
#define B_BYTES (BK * BP * 2)       // 33792 per chunk
#define A_OFF 128
#define B_OFF (A_OFF + 2 * A_BYTES) // 36992
#define K3_SMEM (B_OFF + NCHUNK * B_BYTES)  // 172160

__global__ void __launch_bounds__(NT, 1) k3_mma(const float* __restrict__ x,
                                                const int* __restrict__ o32,
                                                float* __restrict__ out) {
    extern __shared__ char smem[];
    uint32_t sbase = smem_u32(smem);
    int* so_s = (int*)smem;
    __half* Asm = (__half*)(smem + A_OFF);
    const uint32_t aA = sbase + A_OFF;
    const uint32_t aB = sbase + B_OFF;

    int tid = threadIdx.x;
    int lane = tid & 31;
    int wid = tid >> 5;
    int wm = wid >> 3;   // 0..1
    int wn = wid & 7;    // 0..7

    if (tid < S) {
        int stride = (o32[1] == 0) ? 2 : 1;
        so_s[tid] = o32[tid * stride];
    }

    // ---- load ALL of B once (135 KB) ----
    {
        const char* src = (const char*)g_Bimg;
        for (int i = tid; i < (NCHUNK * B_BYTES) / 16; i += NT)
            CP_ASYNC16(aB + (uint32_t)(i * 16), src + i * 16);
        CP_COMMIT();
    }

    // A load geometry: 4 threads per row, 16 consecutive floats each
    int arow = tid >> 2;         // 0..127
    int acol = (tid & 3) * 16;   // 0,16,32,48

    uint32_t aoff[4];
#pragma unroll
    for (int ms = 0; ms < 4; ms++)
        aoff[ms] = (uint32_t)(((wm * 64 + ms * 16 + (lane & 15)) * AP + ((lane >> 4) << 3)) * 2);
    uint32_t boff[4];
#pragma unroll
    for (int ns = 0; ns < 4; ns++)
        boff[ns] = (uint32_t)(((lane & 15) * BP + wn * 32 + ns * 8) * 2);

    float acc[4][4][4];
#pragma unroll
    for (int i = 0; i < 4; i++)
#pragma unroll
        for (int j = 0; j < 4; j++)
#pragma unroll
            for (int r = 0; r < 4; r++) acc[i][j][r] = 0.0f;

    // number of (tile,chunk) steps for this CTA
    int ntile_local = 0;
    for (int t = blockIdx.x; t < NTILE; t += GRID) ntile_local++;
    int ncc = ntile_local * NCHUNK;
    if (ncc == 0) return;

    // prologue: load A for cc=0 (tile = blockIdx.x, chunk 0)
    float4 pre[4];
    {
        const float* ag = x + (size_t)((size_t)blockIdx.x * BM + arow) * C + acol;
#pragma unroll
        for (int j = 0; j < 4; j++) pre[j] = __ldg((const float4*)(ag + j * 4));
        __half* dst = Asm + (size_t)arow * AP + acol;
#pragma unroll
        for (int j = 0; j < 4; j++) {
            __half2 a = __float22half2_rn(make_float2(pre[j].x, pre[j].y));
            __half2 b = __float22half2_rn(make_float2(pre[j].z, pre[j].w));
            *(uint2*)(dst + j * 4) = make_uint2(*(uint32_t*)&a, *(uint32_t*)&b);
        }
    }
    CP_WAIT0();
    __syncthreads();

#pragma unroll 1
    for (int cc = 0; cc < ncc; cc++) {
        int chunk = cc & (NCHUNK - 1);
        int tile_i = cc >> 2;                       // local tile index
        int buf = cc & 1;
        uint32_t abuf = aA + (uint32_t)(buf * A_BYTES);
        uint32_t bbuf = aB + (uint32_t)(chunk * B_BYTES);

        // prefetch A for cc+1
        if (cc < ncc - 1) {
            int nchunk = (cc + 1) & (NCHUNK - 1);
            int ntile = (cc + 1) >> 2;
            size_t grow = (size_t)(blockIdx.x + ntile * GRID) * BM + arow;
            const float* ag = x + grow * C + nchunk * BK + acol;
#pragma unroll
            for (int j = 0; j < 4; j++) pre[j] = __ldg((const float4*)(ag + j * 4));
        }

        // ---- compute chunk against resident B ----
#pragma unroll
        for (int kk = 0; kk < BK; kk += 16) {
            uint32_t bf[4][2];
#pragma unroll
            for (int ns = 0; ns < 4; ns++)
                LDSM_X2_T(bf[ns][0], bf[ns][1], bbuf + boff[ns] + (uint32_t)(kk * BP * 2));
#pragma unroll
            for (int ms = 0; ms < 4; ms++) {
                uint32_t af[4];
                LDSM_X4(af[0], af[1], af[2], af[3], abuf + aoff[ms] + (uint32_t)(kk * 2));
#pragma unroll
                for (int ns = 0; ns < 4; ns++) MMA_F16(acc[ms][ns], af, bf[ns]);
            }
        }

        // store prefetched A into other buffer
        if (cc < ncc - 1) {
            __half* dst = Asm + (size_t)((buf ^ 1) * (A_BYTES / 2)) + (size_t)arow * AP + acol;
#pragma unroll
            for (int j = 0; j < 4; j++) {
                __half2 a = __float22half2_rn(make_float2(pre[j].x, pre[j].y));
                __half2 b = __float22half2_rn(make_float2(pre[j].z, pre[j].w));
                *(uint2*)(dst + j * 4) = make_uint2(*(uint32_t*)&a, *(uint32_t*)&b);
            }
        }
        __syncthreads();

        // ---- epilogue at end of each tile ----
        if (chunk == NCHUNK - 1) {
            int m0 = (blockIdx.x + tile_i * GRID) * BM;
            int r0 = lane >> 2;
            int cq = (lane & 3) * 2;
#pragma unroll
            for (int ms = 0; ms < 4; ms++) {
                int row = m0 + wm * 64 + ms * 16 + r0;
                int s0 = 0, s1 = 0;
                while (row >= so_s[s0]) s0++;
                while (row + 8 >= so_s[s1]) s1++;
                const float* ct0 = g_ctab + s0 * C;
                const float* ct1 = g_ctab + s1 * C;
                float* o0 = out + (size_t)row * C;
                float* o1 = out + (size_t)(row + 8) * C;
#pragma unroll
                for (int ns = 0; ns < 4; ns++) {
                    int col = wn * 32 + ns * 8 + cq;
                    float2 ca = *(const float2*)&ct0[col];
                    float2 cb = *(const float2*)&ct1[col];
                    float2 va, vb;
                    va.x = fmaxf(acc[ms][ns][0] + ca.x, 0.0f);
                    va.y = fmaxf(acc[ms][ns][1] + ca.y, 0.0f);
                    vb.x = fmaxf(acc[ms][ns][2] + cb.x, 0.0f);
                    vb.y = fmaxf(acc[ms][ns][3] + cb.y, 0.0f);
                    *(float2*)&o0[col] = va;
                    *(float2*)&o1[col] = vb;
                    acc[ms][ns][0] = 0.0f; acc[ms][ns][1] = 0.0f;
                    acc[ms][ns][2] = 0.0f; acc[ms][ns][3] = 0.0f;
                }
            }
        }
    }
}

// ---------------------------------------------------------------------------
extern "C" void kernel_launch(void* const* d_in, const int* in_sizes, int n_in,
                              void* d_out, int out_size) {
    const float* x     = (const float*)d_in[0];
    const int*   o     = (const int*)d_in[1];
    const float* W2    = (const float*)d_in[2];
    const float* b2    = (const float*)d_in[3];
    const float* W1    = (const float*)d_in[4];
    const float* b1    = (const float*)d_in[5];
    const float* gamma = (const float*)d_in[6];
    const float* beta  = (const float*)d_in[7];
    const float* rm    = (const float*)d_in[8];
    const float* rv    = (const float*)d_in[9];
    float* out = (float*)d_out;

    cudaFuncSetAttribute(k3_mma, cudaFuncAttributeMaxDynamicSharedMemorySize, K3_SMEM);

    kw_split<<<256, 256>>>(W1, gamma, rv);
    k1_segsum<<<NROWS / 128, 256>>>(x, o);
    k2a<<<S * 8, 256>>>(o, W2, b2);
    k2b<<<S * 8, 256>>>(W1, b1, gamma, beta, rm, rv);
    k3_mma<<<GRID, NT, K3_SMEM>>>(x, o, out);
}

// round 8
// speedup vs baseline: 3.6592x; 1.1097x over previous
#include <cuda_runtime.h>
#include <cuda_fp16.h>
#include <cstdint>
#include <math.h>

#define NROWS 262144
#define C 256
#define S 16

#define BM 128
#define BK 64
#define NCHUNK 4            // K=256 / BK
#define NT 512              // threads per CTA
#define NTILE (NROWS / BM)  // 2048
#define GRID 148
#define AP 72               // A smem row stride in halves (64 + 8 pad)
#define BP 264              // B smem row stride in halves (256 + 8 pad)

// ---------------- scratch ---------------------------------------------------
__device__ float g_segsum[S * C];
__device__ float g_h[S * C];
__device__ float g_ctab[S * C];
// B image: [chunk][k=64][BP] fp16 of (W1a * diag(bn_scale)), exact smem layout
__device__ __half g_Bimg[NCHUNK * BK * BP];

// ---------------- helpers ---------------------------------------------------
__device__ __forceinline__ uint32_t smem_u32(const void* p) {
    uint32_t a;
    asm("{ .reg .u64 t; cvta.to.shared.u64 t, %1; cvt.u32.u64 %0, t; }" : "=r"(a) : "l"(p));
    return a;
}
#define CP_ASYNC16(dst, src) asm volatile("cp.async.cg.shared.global [%0], [%1], 16;" :: "r"(dst), "l"(src))
#define CP_COMMIT() asm volatile("cp.async.commit_group;" ::: "memory")
#define CP_WAIT0()  asm volatile("cp.async.wait_group 0;" ::: "memory")
#define BAR_HALF(id) asm volatile("bar.sync %0, 256;" :: "r"(id) : "memory")

#define LDSM_X4(r0, r1, r2, r3, addr) \
    asm volatile("ldmatrix.sync.aligned.m8n8.x4.shared.b16 {%0,%1,%2,%3}, [%4];" \
                 : "=r"(r0), "=r"(r1), "=r"(r2), "=r"(r3) : "r"(addr))
#define LDSM_X2_T(r0, r1, addr) \
    asm volatile("ldmatrix.sync.aligned.m8n8.x2.trans.shared.b16 {%0,%1}, [%2];" \
                 : "=r"(r0), "=r"(r1) : "r"(addr))

#define MMA_F16(d, a, b) \
    asm volatile("mma.sync.aligned.m16n8k16.row.col.f32.f16.f16.f32 " \
                 "{%0,%1,%2,%3}, {%4,%5,%6,%7}, {%8,%9}, {%0,%1,%2,%3};" \
                 : "+f"((d)[0]), "+f"((d)[1]), "+f"((d)[2]), "+f"((d)[3]) \
                 : "r"((a)[0]), "r"((a)[1]), "r"((a)[2]), "r"((a)[3]), "r"((b)[0]), "r"((b)[1]))

// ---------------------------------------------------------------------------
// kw: W1a rows scaled by BN scale per column, fp16 chunk images; zeros segsum
__global__ void kw_split(const float* __restrict__ W1,
                         const float* __restrict__ gamma,
                         const float* __restrict__ rv) {
    int k = blockIdx.x;   // 0..255
    int n = threadIdx.x;  // 0..255
    if (k < S) g_segsum[k * C + n] = 0.0f;
    float sc = gamma[n] * rsqrtf(rv[n] + 1e-5f);
    float w = W1[k * C + n] * sc;
    int c = k >> 6, kk = k & 63;
    g_Bimg[(c * BK + kk) * BP + n] = __float2half_rn(w);
    if (n < BP - 256)
        g_Bimg[(c * BK + kk) * BP + 256 + n] = __float2half_rn(0.0f);
}

// segment sums
__global__ void __launch_bounds__(256) k1_segsum(const float* __restrict__ x,
                                                 const int* __restrict__ o32) {
    __shared__ int so[S];
    if (threadIdx.x < S) {
        int stride = (o32[1] == 0) ? 2 : 1;
        so[threadIdx.x] = o32[threadIdx.x * stride];
    }
    __syncthreads();
    int t = threadIdx.x;
    int g0 = blockIdx.x * 128;
    int s = 0;
    while (g0 >= so[s]) s++;
    int r = 0;
    while (r < 128) {
        int end = so[s] - g0;
        if (end > 128) end = 128;
        float acc = 0.0f;
        for (; r + 4 <= end; r += 4) {
            acc += __ldg(&x[(size_t)(g0 + r + 0) * C + t]) + __ldg(&x[(size_t)(g0 + r + 1) * C + t]) +
                   __ldg(&x[(size_t)(g0 + r + 2) * C + t]) + __ldg(&x[(size_t)(g0 + r + 3) * C + t]);
        }
        for (; r < end; r++) acc += __ldg(&x[(size_t)(g0 + r) * C + t]);
        atomicAdd(&g_segsum[s * C + t], acc);
        s++;
    }
}

// k2a: h[s, col] = relu(mean[s] @ W2 + b2), grid = S*8
__global__ void __launch_bounds__(256) k2a(const int* __restrict__ o32,
                                           const float* __restrict__ W2,
                                           const float* __restrict__ b2) {
    __shared__ float mean_s[C];
    __shared__ float red[256];
    int s = blockIdx.x >> 3, g = blockIdx.x & 7;
    int tid = threadIdx.x;
    int stride = (o32[1] == 0) ? 2 : 1;
    int oe = o32[s * stride];
    int ob = (s > 0) ? o32[(s - 1) * stride] : 0;
    float inv = 1.0f / (float)(oe - ob);
    mean_s[tid] = g_segsum[s * C + tid] * inv;
    __syncthreads();
    int col = g * 32 + (tid & 31);
    int kc = tid >> 5;
    float acc = 0.0f;
#pragma unroll 8
    for (int i = 0; i < 32; i++)
        acc = fmaf(mean_s[kc * 32 + i], __ldg(&W2[(size_t)(kc * 32 + i) * C + col]), acc);
    red[tid] = acc;
    __syncthreads();
    if (tid < 32) {
        float t = red[tid];
#pragma unroll
        for (int j = 1; j < 8; j++) t += red[j * 32 + tid];
        int c0 = g * 32 + tid;
        g_h[s * C + c0] = fmaxf(t + __ldg(&b2[c0]), 0.0f);
    }
}

// k2b: ctab[s, col] = (h[s]@W1b + b1)*sc + beta - rm*sc
__global__ void __launch_bounds__(256) k2b(const float* __restrict__ W1,
                                           const float* __restrict__ b1,
                                           const float* __restrict__ gamma,
                                           const float* __restrict__ beta,
                                           const float* __restrict__ rm,
                                           const float* __restrict__ rv) {
    __shared__ float h_s[C];
    __shared__ float red[256];
    int s = blockIdx.x >> 3;
    int g = blockIdx.x & 7;
    int tid = threadIdx.x;
    h_s[tid] = g_h[s * C + tid];
    __syncthreads();
    int col = g * 32 + (tid & 31);
    int kc = tid >> 5;
    float acc = 0.0f;
#pragma unroll 8
    for (int i = 0; i < 32; i++)
        acc = fmaf(h_s[kc * 32 + i], __ldg(&W1[(size_t)(C + kc * 32 + i) * C + col]), acc);
    red[tid] = acc;
    __syncthreads();
    if (tid < 32) {
        float t = red[tid];
#pragma unroll
        for (int j = 1; j < 8; j++) t += red[j * 32 + tid];
        int c0 = g * 32 + tid;
        float sc = gamma[c0] * rsqrtf(rv[c0] + 1e-5f);
        g_ctab[s * C + c0] = (t + __ldg(&b1[c0])) * sc + beta[c0] - rm[c0] * sc;
    }
}

// ---------------------------------------------------------------------------
// k3: persistent fp16 mma.sync GEMM, B + ctab resident in smem, CTA split into
// two independent 256-thread halves synced by named barriers (epilogue of one
// half overlaps MMAs of the other).
// smem: [so 128B][ctab 16K][A: 2 buf x 128 x AP halves][B: 4 x 64 x BP halves]
// ---------------------------------------------------------------------------
#define A_BYTES (BM * AP * 2)          // 18432
#define B_BYTES (BK * BP * 2)          // 33792 per chunk
#define CT_OFF 128
#define A_OFF (CT_OFF + 16384)         // 16512
#define B_OFF (A_OFF + 2 * A_BYTES)    // 53376
#define K3_SMEM (B_OFF + NCHUNK * B_BYTES)  // 188544

__global__ void __launch_bounds__(NT, 1) k3_mma(const float* __restrict__ x,
                                                const int* __restrict__ o32,
                                                float* __restrict__ out) {
    extern __shared__ char smem[];
    uint32_t sbase = smem_u32(smem);
    int* so_s = (int*)smem;
    float* ct_s = (float*)(smem + CT_OFF);
    __half* Asm = (__half*)(smem + A_OFF);
    const uint32_t aA = sbase + A_OFF;
    const uint32_t aB = sbase + B_OFF;

    int tid = threadIdx.x;
    int lane = tid & 31;
    int wid = tid >> 5;
    int wm = wid >> 3;   // 0..1 : which half
    int wn = wid & 7;    // 0..7
    int barid = 1 + wm;  // named barrier per half

    if (tid < S) {
        int stride = (o32[1] == 0) ? 2 : 1;
        so_s[tid] = o32[tid * stride];
    }
    // ctab -> smem (16 KB)
    {
        const float4* src = (const float4*)g_ctab;
        float4* dst = (float4*)ct_s;
        dst[tid] = __ldg(&src[tid]);
        dst[tid + NT] = __ldg(&src[tid + NT]);
    }
    // ---- load ALL of B once (135 KB) ----
    {
        const char* src = (const char*)g_Bimg;
        for (int i = tid; i < (NCHUNK * B_BYTES) / 16; i += NT)
            CP_ASYNC16(aB + (uint32_t)(i * 16), src + i * 16);
        CP_COMMIT();
    }

    // A load geometry: 4 threads per row, 16 consecutive floats each
    int arow = tid >> 2;         // 0..127 (tids 0-255 -> rows 0-63 = lower half)
    int acol = (tid & 3) * 16;

    uint32_t aoff[4];
#pragma unroll
    for (int ms = 0; ms < 4; ms++)
        aoff[ms] = (uint32_t)(((wm * 64 + ms * 16 + (lane & 15)) * AP + ((lane >> 4) << 3)) * 2);
    uint32_t boff[4];
#pragma unroll
    for (int ns = 0; ns < 4; ns++)
        boff[ns] = (uint32_t)(((lane & 15) * BP + wn * 32 + ns * 8) * 2);

    float acc[4][4][4];
#pragma unroll
    for (int i = 0; i < 4; i++)
#pragma unroll
        for (int j = 0; j < 4; j++)
#pragma unroll
            for (int r = 0; r < 4; r++) acc[i][j][r] = 0.0f;

    int ntile_local = 0;
    for (int t = blockIdx.x; t < NTILE; t += GRID) ntile_local++;
    int ncc = ntile_local * NCHUNK;
    if (ncc == 0) return;

    // prologue: load A for cc=0
    float4 pre[4];
    {
        const float* ag = x + (size_t)((size_t)blockIdx.x * BM + arow) * C + acol;
#pragma unroll
        for (int j = 0; j < 4; j++) pre[j] = __ldg((const float4*)(ag + j * 4));
        __half* dst = Asm + (size_t)arow * AP + acol;
#pragma unroll
        for (int j = 0; j < 4; j++) {
            __half2 a = __float22half2_rn(make_float2(pre[j].x, pre[j].y));
            __half2 b = __float22half2_rn(make_float2(pre[j].z, pre[j].w));
            *(uint2*)(dst + j * 4) = make_uint2(*(uint32_t*)&a, *(uint32_t*)&b);
        }
    }
    CP_WAIT0();
    __syncthreads();   // B + ctab + so + A(0) all visible; halves drift after this

#pragma unroll 1
    for (int cc = 0; cc < ncc; cc++) {
        int chunk = cc & (NCHUNK - 1);
        int tile_i = cc >> 2;
        int buf = cc & 1;
        uint32_t abuf = aA + (uint32_t)(buf * A_BYTES);
        uint32_t bbuf = aB + (uint32_t)(chunk * B_BYTES);

        // prefetch A for cc+1
        if (cc < ncc - 1) {
            int nchunk = (cc + 1) & (NCHUNK - 1);
            int ntile = (cc + 1) >> 2;
            size_t grow = (size_t)(blockIdx.x + ntile * GRID) * BM + arow;
            const float* ag = x + grow * C + nchunk * BK + acol;
#pragma unroll
            for (int j = 0; j < 4; j++) pre[j] = __ldg((const float4*)(ag + j * 4));
        }

        // ---- compute chunk against resident B ----
#pragma unroll
        for (int kk = 0; kk < BK; kk += 16) {
            uint32_t bf[4][2];
#pragma unroll
            for (int ns = 0; ns < 4; ns++)
                LDSM_X2_T(bf[ns][0], bf[ns][1], bbuf + boff[ns] + (uint32_t)(kk * BP * 2));
#pragma unroll
            for (int ms = 0; ms < 4; ms++) {
                uint32_t af[4];
                LDSM_X4(af[0], af[1], af[2], af[3], abuf + aoff[ms] + (uint32_t)(kk * 2));
#pragma unroll
                for (int ns = 0; ns < 4; ns++) MMA_F16(acc[ms][ns], af, bf[ns]);
            }
        }

        // store prefetched A into other buffer (own half's rows only)
        if (cc < ncc - 1) {
            __half* dst = Asm + (size_t)((buf ^ 1) * (A_BYTES / 2)) + (size_t)arow * AP + acol;
#pragma unroll
            for (int j = 0; j < 4; j++) {
                __half2 a = __float22half2_rn(make_float2(pre[j].x, pre[j].y));
                __half2 b = __float22half2_rn(make_float2(pre[j].z, pre[j].w));
                *(uint2*)(dst + j * 4) = make_uint2(*(uint32_t*)&a, *(uint32_t*)&b);
            }
        }
        BAR_HALF(barid);   // half-local barrier: other half drifts

        // ---- epilogue at end of each tile (overlaps other half's MMAs) ----
        if (chunk == NCHUNK - 1) {
            int m0 = (blockIdx.x + tile_i * GRID) * BM;
            int r0 = lane >> 2;
            int cq = (lane & 3) * 2;
#pragma unroll
            for (int ms = 0; ms < 4; ms++) {
                int row = m0 + wm * 64 + ms * 16 + r0;
                int s0 = 0, s1 = 0;
                while (row >= so_s[s0]) s0++;
                while (row + 8 >= so_s[s1]) s1++;
                const float* ct0 = ct_s + s0 * C;
                const float* ct1 = ct_s + s1 * C;
                float* o0 = out + (size_t)row * C;
                float* o1 = out + (size_t)(row + 8) * C;
#pragma unroll
                for (int ns = 0; ns < 4; ns++) {
                    int col = wn * 32 + ns * 8 + cq;
                    float2 ca = *(const float2*)&ct0[col];
                    float2 cb = *(const float2*)&ct1[col];
                    float2 va, vb;
                    va.x = fmaxf(acc[ms][ns][0] + ca.x, 0.0f);
                    va.y = fmaxf(acc[ms][ns][1] + ca.y, 0.0f);
                    vb.x = fmaxf(acc[ms][ns][2] + cb.x, 0.0f);
                    vb.y = fmaxf(acc[ms][ns][3] + cb.y, 0.0f);
                    *(float2*)&o0[col] = va;
                    *(float2*)&o1[col] = vb;
                    acc[ms][ns][0] = 0.0f; acc[ms][ns][1] = 0.0f;
                    acc[ms][ns][2] = 0.0f; acc[ms][ns][3] = 0.0f;
                }
            }
        }
    }
}

// ---------------------------------------------------------------------------
extern "C" void kernel_launch(void* const* d_in, const int* in_sizes, int n_in,
                              void* d_out, int out_size) {
    const float* x     = (const float*)d_in[0];
    const int*   o     = (const int*)d_in[1];
    const float* W2    = (const float*)d_in[2];
    const float* b2    = (const float*)d_in[3];
    const float* W1    = (const float*)d_in[4];
    const float* b1    = (const float*)d_in[5];
    const float* gamma = (const float*)d_in[6];
    const float* beta  = (const float*)d_in[7];
    const float* rm    = (const float*)d_in[8];
    const float* rv    = (const float*)d_in[9];
    float* out = (float*)d_out;

    cudaFuncSetAttribute(k3_mma, cudaFuncAttributeMaxDynamicSharedMemorySize, K3_SMEM);

    kw_split<<<256, 256>>>(W1, gamma, rv);
    k1_segsum<<<NROWS / 128, 256>>>(x, o);
    k2a<<<S * 8, 256>>>(o, W2, b2);
    k2b<<<S * 8, 256>>>(W1, b1, gamma, beta, rm, rv);
    k3_mma<<<GRID, NT, K3_SMEM>>>(x, o, out);
}